// round 15
// baseline (speedup 1.0000x reference)
#include <cuda_runtime.h>
#include <cuda_fp16.h>
#include <mma.h>
#include <math.h>
#include <stdint.h>

using namespace nvcuda;

#define N0 4096
#define D 320
#define NNZMAX 2200000
#define CBLOCKS 128
#define CITERS 30

// P arena geometry (per level): rows/LDP padded to 64, K-loop bound padded to 16
// ns   : 4096 3686 2580 1548 774
// n16  : 4096 3696 2592 1552 784
// pad64: 4096 3712 2624 1600 832
#define P_TOTAL 40693760ULL

// ---------------- device global scratch (no allocation allowed) ----------------
__device__ int g_rp[5][N0 + 1];
__device__ int g_ci[5][NNZMAX];
__device__ int g_deg[N0 + 1];
__device__ __align__(16) float g_v[N0];
__device__ __align__(16) float g_pv[(CITERS + 1) * N0];
__device__ __align__(16) float g_XC[N0 * D];
__device__ __align__(16) float g_Wh[N0 * D];
__device__ __align__(16) __half g_WhH[N0 * D];
__device__ float g_f1[N0];
__device__ float g_f2[N0];
__device__ float g_Z[N0];
__device__ __align__(16) __half g_P[P_TOTAL];  // zero-initialized; non-edge entries stay 0
__device__ __align__(16) float g_orgX[N0 * D];
__device__ __align__(16) float g_down[4][N0 * D];
__device__ __align__(16) float g_Hbuf[N0 * D];
__device__ __align__(16) float g_Ubuf[N0 * D];
__device__ float g_scores[N0];
__device__ float g_vals[N0];
__device__ int g_idx[4][N0];
__device__ int g_rankL[4][N0];
__device__ unsigned g_barcnt = 0;
__device__ unsigned g_bargen = 0;

// ---------------- CSR build from dense A (level 0) ----------------
__global__ void csr0_count(const float* __restrict__ A) {
    int r = blockIdx.x;
    int cnt = 0;
    for (int c = threadIdx.x; c < N0; c += blockDim.x)
        cnt += (A[(size_t)r * N0 + c] > 0.f) ? 1 : 0;
    __shared__ int s[256];
    s[threadIdx.x] = cnt;
    __syncthreads();
    for (int st = 128; st > 0; st >>= 1) {
        if (threadIdx.x < st) s[threadIdx.x] += s[threadIdx.x + st];
        __syncthreads();
    }
    if (threadIdx.x == 0) g_deg[r] = s[0];
}

__global__ void scan_kernel(int* __restrict__ rp, int n) {
    __shared__ int sh[1024];
    int tid = threadIdx.x;
    int loc[4];
    int s = 0;
    int base = tid * 4;
#pragma unroll
    for (int k = 0; k < 4; k++) {
        int i = base + k;
        int vv = (i < n) ? g_deg[i] : 0;
        loc[k] = s;
        s += vv;
    }
    sh[tid] = s;
    __syncthreads();
    for (int off = 1; off < 1024; off <<= 1) {
        int v = (tid >= off) ? sh[tid - off] : 0;
        __syncthreads();
        sh[tid] += v;
        __syncthreads();
    }
    int pre = (tid > 0) ? sh[tid - 1] : 0;
#pragma unroll
    for (int k = 0; k < 4; k++) {
        int i = base + k;
        if (i < n) rp[i] = pre + loc[k];
    }
    if (tid == 1023) rp[n] = sh[1023];
}

__global__ void csr0_fill(const float* __restrict__ A, const int* __restrict__ rp,
                          int* __restrict__ ci) {
    int r = blockIdx.x;
    __shared__ int s_off;
    __shared__ int wcnt[8];
    if (threadIdx.x == 0) s_off = rp[r];
    __syncthreads();
    for (int c0 = 0; c0 < N0; c0 += 256) {
        int c = c0 + threadIdx.x;
        bool nz = (A[(size_t)r * N0 + c] > 0.f);
        unsigned b = __ballot_sync(0xffffffffu, nz);
        int lane = threadIdx.x & 31, w = threadIdx.x >> 5;
        if (lane == 0) wcnt[w] = __popc(b);
        __syncthreads();
        if (threadIdx.x == 0) {
            int a = s_off;
            for (int i = 0; i < 8; i++) {
                int t = wcnt[i];
                wcnt[i] = a;
                a += t;
            }
            s_off = a;
        }
        __syncthreads();
        if (nz) ci[wcnt[w] + __popc(b & ((1u << lane) - 1))] = c;
        __syncthreads();
    }
}

// ---------------- fused centrality (30 power iterations, one kernel) ----------------
__device__ __forceinline__ void grid_barrier() {
    __threadfence();
    __syncthreads();
    if (threadIdx.x == 0) {
        unsigned gen = *((volatile unsigned*)&g_bargen);
        unsigned t = atomicAdd(&g_barcnt, 1u);
        if (t == (unsigned)(CBLOCKS - 1)) {
            g_barcnt = 0;
            __threadfence();
            atomicAdd(&g_bargen, 1u);
        } else {
            while (*((volatile unsigned*)&g_bargen) == gen) {
            }
        }
    }
    __syncthreads();
    __threadfence();
}

__global__ void __launch_bounds__(1024, 1)
centrality_fused(const int* __restrict__ rp, const int* __restrict__ ci) {
    int tid = threadIdx.x;
    int w = tid >> 5, lane = tid & 31;
    int row = blockIdx.x * 32 + w;
    __shared__ float red[1024];
    if (tid < 32) g_pv[blockIdx.x * 32 + tid] = 1.f / (float)N0;
    grid_barrier();
    float inv = 1.0f;
    int s = rp[row], e = rp[row + 1];
    for (int t = 0; t < CITERS; t++) {
        const float* bufA = g_pv + (size_t)t * N0;
        float* bufB = g_pv + (size_t)(t + 1) * N0;
        float acc = 0.f;
        for (int k = s + lane; k < e; k += 32) acc += __fmul_rn(bufA[ci[k]], inv);
        for (int o = 16; o; o >>= 1) acc += __shfl_down_sync(0xffffffffu, acc, o);
        if (lane == 0) bufB[row] = acc;
        grid_barrier();
        float ss = 0.f;
        for (int i = tid; i < N0; i += 1024) {
            float tt = bufB[i];
            ss += tt * tt;
        }
        red[tid] = ss;
        __syncthreads();
        for (int st = 512; st > 0; st >>= 1) {
            if (tid < st) red[tid] += red[tid + st];
            __syncthreads();
        }
        inv = 1.f / (sqrtf(red[0]) + 1e-12f);
        __syncthreads();
    }
    if (tid < 32) {
        int i = blockIdx.x * 32 + tid;
        g_v[i] = __fmul_rn(g_pv[(size_t)CITERS * N0 + i], inv);
    }
}

// ---------------- misc elementwise ----------------
__global__ void concat_xc_kernel(const float* __restrict__ X, const float* __restrict__ v,
                                 float* __restrict__ XC) {
    int i = blockIdx.x * blockDim.x + threadIdx.x;
    if (i >= N0 * D) return;
    int r = i / D, d = i % D;
    XC[i] = (d < D - 1) ? X[(size_t)r * (D - 1) + d] : v[r];
}

__global__ void unpool_fused_kernel(const float* __restrict__ H, const float* __restrict__ Z,
                                    const float* __restrict__ b, const int* __restrict__ rank,
                                    float* __restrict__ U, int nl) {
    int i = blockIdx.x * blockDim.x + threadIdx.x;
    if (i >= nl * D) return;
    int r = i / D, d = i % D;
    int rk = rank[r];
    float o = 0.f;
    if (rk >= 0) {
        float z = Z[(size_t)rk * D + d] + b[d];
        o = H[(size_t)rk * D + d] * (1.f / (1.f + expf(-z)));
    }
    U[i] = o;
}

__global__ void poolx_kernel(const float* __restrict__ G, const int* __restrict__ idx,
                             const float* __restrict__ vals, float* __restrict__ nx, int nk) {
    int i = blockIdx.x * blockDim.x + threadIdx.x;
    if (i >= nk * D) return;
    int r = i / D, d = i % D;
    nx[i] = G[(size_t)idx[r] * D + d] * vals[r];
}

__global__ void rank_init_kernel(int* __restrict__ rank, int pn) {
    int i = blockIdx.x * blockDim.x + threadIdx.x;
    if (i < pn) rank[i] = -1;
}

__global__ void rank_set_kernel(const int* __restrict__ idx, int* __restrict__ rank, int nk) {
    int i = blockIdx.x * blockDim.x + threadIdx.x;
    if (i < nk) rank[idx[i]] = i;
}

// ---------------- pooled CSR build ----------------
__global__ void pool_deg_kernel(const int* __restrict__ prp, const int* __restrict__ pci,
                                const int* __restrict__ idx, const int* __restrict__ rank,
                                int nk) {
    int w = (blockIdx.x * blockDim.x + threadIdx.x) >> 5;
    if (w >= nk) return;
    int lane = threadIdx.x & 31;
    int p = idx[w];
    int s = prp[p], e = prp[p + 1];
    int cnt = 0;
    for (int k = s + lane; k < e; k += 32) cnt += (rank[pci[k]] >= 0) ? 1 : 0;
    for (int o = 16; o; o >>= 1) cnt += __shfl_down_sync(0xffffffffu, cnt, o);
    if (lane == 0) g_deg[w] = cnt;
}

__global__ void pool_fill_kernel(const int* __restrict__ prp, const int* __restrict__ pci,
                                 const int* __restrict__ nrp, int* __restrict__ nci,
                                 const int* __restrict__ idx, const int* __restrict__ rank,
                                 int nk) {
    int w = (blockIdx.x * blockDim.x + threadIdx.x) >> 5;
    if (w >= nk) return;
    int lane = threadIdx.x & 31;
    int p = idx[w];
    int s = prp[p], e = prp[p + 1];
    int wbase = nrp[w];
    for (int k0 = s; k0 < e; k0 += 32) {
        int k = k0 + lane;
        int rk = -1;
        if (k < e) rk = rank[pci[k]];
        bool keep = (rk >= 0);
        unsigned b = __ballot_sync(0xffffffffu, keep);
        if (keep) nci[wbase + __popc(b & ((1u << lane) - 1))] = rk;
        wbase += __popc(b);
    }
}

// ---------------- pool scoring + sort (top-k) ----------------
__global__ void pool_score_kernel(const float* __restrict__ Xf, const float* __restrict__ pw,
                                  const float* __restrict__ pb, float* __restrict__ scores, int n) {
    int w = (blockIdx.x * blockDim.x + threadIdx.x) >> 5;
    if (w >= n) return;
    int lane = threadIdx.x & 31;
    float s = 0.f;
    for (int d = lane; d < D; d += 32) s += Xf[(size_t)w * D + d] * pw[d];
    for (int o = 16; o; o >>= 1) s += __shfl_down_sync(0xffffffffu, s, o);
    if (lane == 0) {
        float z = (s + pb[0]) / 100.f;
        scores[w] = 1.f / (1.f + expf(-z));
    }
}

__global__ void sort_kernel(const float* __restrict__ scores, float* __restrict__ vals,
                            int* __restrict__ idxo, int n, int P) {
    __shared__ float sv[4096];
    __shared__ int si[4096];
    int tid = threadIdx.x;
    for (int i = tid; i < P; i += 1024) {
        bool ok = (i < n);
        sv[i] = ok ? scores[i] : -INFINITY;
        si[i] = ok ? i : 0x7fffffff;
    }
    __syncthreads();
    for (int k = 2; k <= P; k <<= 1) {
        for (int j = k >> 1; j > 0; j >>= 1) {
            for (int i = tid; i < P; i += 1024) {
                int ixj = i ^ j;
                if (ixj > i) {
                    float s1 = sv[i], s2 = sv[ixj];
                    int i1 = si[i], i2 = si[ixj];
                    bool firstBetter = (s1 > s2) || (s1 == s2 && i1 < i2);
                    bool desc = ((i & k) == 0);
                    if (desc ? !firstBetter : firstBetter) {
                        sv[i] = s2;
                        sv[ixj] = s1;
                        si[i] = i2;
                        si[ixj] = i1;
                    }
                }
            }
            __syncthreads();
        }
    }
    for (int i = tid; i < n; i += 1024) {
        vals[i] = sv[i];
        idxo[i] = si[i];
    }
}

// ---------------- GEMM: C[M,N] = A[M,K] @ B ; B is [K,N] or (transB) [N,K] ----------------
__global__ void gemm_kernel(const float* __restrict__ A, const float* __restrict__ A2,
                            int Ksplit, const float* __restrict__ B,
                            float* __restrict__ C, __half* __restrict__ Ch,
                            int M, int K, int N, int transB) {
    __shared__ __align__(16) float As[16][68];
    __shared__ __align__(16) float Bs[16][68];
    int bm = blockIdx.y * 64, bn = blockIdx.x * 64;
    int tid = threadIdx.x;
    int tx = tid & 15, ty = tid >> 4;
    float acc[4][4] = {};
    for (int k0 = 0; k0 < K; k0 += 16) {
#pragma unroll
        for (int i = tid; i < 1024; i += 256) {
            int kk = i & 15, m = i >> 4;
            int gm = bm + m, gk = k0 + kk;
            float av = 0.f;
            if (gm < M) {
                if (gk < Ksplit)
                    av = A[(size_t)gm * Ksplit + gk];
                else
                    av = A2[(size_t)gm * Ksplit + (gk - Ksplit)];
            }
            As[kk][m] = av;
        }
        if (!transB) {
#pragma unroll
            for (int i = tid; i < 1024; i += 256) {
                int nn = i & 63, kk = i >> 6;
                int gn = bn + nn, gk = k0 + kk;
                Bs[kk][nn] = (gn < N) ? B[(size_t)gk * N + gn] : 0.f;
            }
        } else {
#pragma unroll
            for (int i = tid; i < 1024; i += 256) {
                int kk = i & 15, nn = i >> 4;
                int gn = bn + nn, gk = k0 + kk;
                Bs[kk][nn] = (gn < N) ? B[(size_t)gn * K + gk] : 0.f;
            }
        }
        __syncthreads();
#pragma unroll
        for (int kk = 0; kk < 16; kk++) {
            float4 a4 = *reinterpret_cast<const float4*>(&As[kk][ty * 4]);
            float4 b4 = *reinterpret_cast<const float4*>(&Bs[kk][tx * 4]);
            float av[4] = {a4.x, a4.y, a4.z, a4.w};
            float bv[4] = {b4.x, b4.y, b4.z, b4.w};
#pragma unroll
            for (int i2 = 0; i2 < 4; i2++)
#pragma unroll
                for (int j2 = 0; j2 < 4; j2++) acc[i2][j2] += av[i2] * bv[j2];
        }
        __syncthreads();
    }
#pragma unroll
    for (int i2 = 0; i2 < 4; i2++) {
        int gm = bm + ty * 4 + i2;
        if (gm < M) {
#pragma unroll
            for (int j2 = 0; j2 < 4; j2++) {
                int gn = bn + tx * 4 + j2;
                if (gn < N) {
                    C[(size_t)gm * N + gn] = acc[i2][j2];
                    if (Ch) Ch[(size_t)gm * N + gn] = __float2half(acc[i2][j2]);
                }
            }
        }
    }
}

__global__ void gemm32_kernel(const float* __restrict__ A, const float* __restrict__ B,
                              float* __restrict__ C, __half* __restrict__ Ch,
                              int M, int K, int N, int transB) {
    __shared__ __align__(16) float As[16][36];
    __shared__ __align__(16) float Bs[16][68];
    int bm = blockIdx.y * 32, bn = blockIdx.x * 64;
    int tid = threadIdx.x;
    int tx = tid & 15, ty = tid >> 4;
    float acc[2][4] = {};
    for (int k0 = 0; k0 < K; k0 += 16) {
#pragma unroll
        for (int i = tid; i < 512; i += 256) {
            int kk = i & 15, m = i >> 4;
            int gm = bm + m, gk = k0 + kk;
            As[kk][m] = (gm < M) ? A[(size_t)gm * K + gk] : 0.f;
        }
        if (!transB) {
#pragma unroll
            for (int i = tid; i < 1024; i += 256) {
                int nn = i & 63, kk = i >> 6;
                int gn = bn + nn, gk = k0 + kk;
                Bs[kk][nn] = (gn < N) ? B[(size_t)gk * N + gn] : 0.f;
            }
        } else {
#pragma unroll
            for (int i = tid; i < 1024; i += 256) {
                int kk = i & 15, nn = i >> 4;
                int gn = bn + nn, gk = k0 + kk;
                Bs[kk][nn] = (gn < N) ? B[(size_t)gn * K + gk] : 0.f;
            }
        }
        __syncthreads();
#pragma unroll
        for (int kk = 0; kk < 16; kk++) {
            float a0 = As[kk][ty * 2];
            float a1 = As[kk][ty * 2 + 1];
            float4 b4 = *reinterpret_cast<const float4*>(&Bs[kk][tx * 4]);
            float bv[4] = {b4.x, b4.y, b4.z, b4.w};
#pragma unroll
            for (int j2 = 0; j2 < 4; j2++) {
                acc[0][j2] += a0 * bv[j2];
                acc[1][j2] += a1 * bv[j2];
            }
        }
        __syncthreads();
    }
#pragma unroll
    for (int i2 = 0; i2 < 2; i2++) {
        int gm = bm + ty * 2 + i2;
        if (gm < M) {
#pragma unroll
            for (int j2 = 0; j2 < 4; j2++) {
                int gn = bn + tx * 4 + j2;
                if (gn < N) {
                    C[(size_t)gm * N + gn] = acc[i2][j2];
                    if (Ch) Ch[(size_t)gm * N + gn] = __float2half(acc[i2][j2]);
                }
            }
        }
    }
}

// ---------------- attention coefficients: f1 = Wh@a[:D], f2 = Wh@a[D:] ----------------
__global__ void attn_coef_kernel(const float* __restrict__ Wh, const float* __restrict__ a,
                                 float* __restrict__ f1, float* __restrict__ f2, int n) {
    int w = (blockIdx.x * blockDim.x + threadIdx.x) >> 5;
    if (w >= n) return;
    int lane = threadIdx.x & 31;
    float s1 = 0.f, s2 = 0.f;
    for (int d = lane; d < D; d += 32) {
        float v = Wh[(size_t)w * D + d];
        s1 += v * a[d];
        s2 += v * a[D + d];
    }
    for (int o = 16; o; o >>= 1) {
        s1 += __shfl_down_sync(0xffffffffu, s1, o);
        s2 += __shfl_down_sync(0xffffffffu, s2, o);
    }
    if (lane == 0) {
        f1[w] = s1;
        f2[w] = s2;
    }
}

// zero WhH rows [n, n16) so K-padding of the mma reads 0 (never NaN)
__global__ void whpad_kernel(__half* __restrict__ WhH, int n, int n16) {
    int total = (n16 - n) * D;
    for (int i = threadIdx.x; i < total; i += 256) WhH[(size_t)n * D + i] = __float2half(0.f);
}

// ---------------- P build: scatter softmax numerators (fp16) + consistent Z ----------------
// Non-edge entries of P are永 zero (zero-init + identical edge sets every call).
__global__ void pbuild_kernel(const int* __restrict__ rp, const int* __restrict__ ci,
                              const float* __restrict__ f1, const float* __restrict__ f2,
                              __half* __restrict__ P, int LDP, float* __restrict__ Z) {
    int r = blockIdx.x, tid = threadIdx.x;
    __shared__ float red[256];
    int s = rp[r], e = rp[r + 1];
    float F1 = f1[r];
    // pass 1: exact row max of lrelu(F1 + f2[c])
    float m = -INFINITY;
    for (int k = s + tid; k < e; k += 256) {
        float t = F1 + f2[ci[k]];
        t = (t > 0.f) ? t : 0.2f * t;
        m = fmaxf(m, t);
    }
    red[tid] = m;
    __syncthreads();
    for (int st = 128; st > 0; st >>= 1) {
        if (tid < st) red[tid] = fmaxf(red[tid], red[tid + st]);
        __syncthreads();
    }
    m = red[0];
    __syncthreads();
    // pass 2: p = exp(e - m) -> fp16 scatter; Z sums the ROUNDED values (consistent)
    float Zp = 0.f;
    for (int k = s + tid; k < e; k += 256) {
        int c = ci[k];
        float t = F1 + f2[c];
        t = (t > 0.f) ? t : 0.2f * t;
        __half ph = __float2half(__expf(t - m));
        P[(size_t)r * LDP + c] = ph;
        Zp += __half2float(ph);
    }
    red[tid] = Zp;
    __syncthreads();
    for (int st = 128; st > 0; st >>= 1) {
        if (tid < st) red[tid] += red[tid + st];
        __syncthreads();
    }
    if (tid == 0) Z[r] = red[0];
}

// rows with Z==0 (no neighbors): reference softmax over all-NEG row = uniform 1/n
__global__ void zfix_kernel(__half* __restrict__ P, int LDP, float* __restrict__ Z, int n) {
    int r = blockIdx.x;
    if (Z[r] != 0.f) return;
    for (int c = threadIdx.x; c < n; c += 256) P[(size_t)r * LDP + c] = __float2half(1.f);
    if (threadIdx.x == 0) Z[r] = (float)n;
}

// ---------------- tensor-core SpMM: out = (P @ WhH) * invZ (+ elu / + residual) ----------------
// 64x64 tile, 8 warps (4x2), each warp 16x32 via two 16x16x16 HMMA frags.
__global__ void __launch_bounds__(256) wmma_spmm_kernel(
    const __half* __restrict__ P, int LDP, const __half* __restrict__ B,
    const float* __restrict__ Z, float* __restrict__ out,
    const float* __restrict__ addsrc, int n, int n16, int mode) {
    __shared__ __align__(16) __half As[64][24];
    __shared__ __align__(16) __half Bs[16][72];
    __shared__ __align__(16) float Cs[64][72];
    int tid = threadIdx.x;
    int warp = tid >> 5;
    int wm = warp >> 1, wn = warp & 1;
    int m0 = blockIdx.y * 64, n0 = blockIdx.x * 64;
    wmma::fragment<wmma::matrix_a, 16, 16, 16, __half, wmma::row_major> fa;
    wmma::fragment<wmma::matrix_b, 16, 16, 16, __half, wmma::row_major> fb0, fb1;
    wmma::fragment<wmma::accumulator, 16, 16, 16, float> fc0, fc1;
    wmma::fill_fragment(fc0, 0.f);
    wmma::fill_fragment(fc1, 0.f);
    int la = tid * 4;
    int arow = la >> 4, acol = la & 15;
    int brow = la >> 6, bcol = la & 63;
    for (int kt = 0; kt < n16; kt += 16) {
        // stage A tile 64x16 (P rows m0..m0+63; rows >= n are permanently zero)
        *(uint2*)&As[arow][acol] =
            *(const uint2*)(P + (size_t)(m0 + arow) * LDP + kt + acol);
        // stage B tile 16x64 (WhH rows kt..kt+15; rows n..n16 zeroed by whpad)
        *(uint2*)&Bs[brow][bcol] =
            *(const uint2*)(B + (size_t)(kt + brow) * D + n0 + bcol);
        __syncthreads();
        wmma::load_matrix_sync(fa, &As[wm * 16][0], 24);
        wmma::load_matrix_sync(fb0, &Bs[0][wn * 32], 72);
        wmma::load_matrix_sync(fb1, &Bs[0][wn * 32 + 16], 72);
        wmma::mma_sync(fc0, fa, fb0, fc0);
        wmma::mma_sync(fc1, fa, fb1, fc1);
        __syncthreads();
    }
    wmma::store_matrix_sync(&Cs[wm * 16][wn * 32], fc0, 72, wmma::mem_row_major);
    wmma::store_matrix_sync(&Cs[wm * 16][wn * 32 + 16], fc1, 72, wmma::mem_row_major);
    __syncthreads();
    for (int i = tid; i < 64 * 64; i += 256) {
        int row = i >> 6, col = i & 63;
        int r = m0 + row;
        if (r < n) {
            float o = Cs[row][col] / Z[r];
            if (mode >= 1) o = (o > 0.f) ? o : expm1f(o);
            if (mode == 2) o += addsrc[(size_t)r * D + n0 + col];
            out[(size_t)r * D + n0 + col] = o;
        }
    }
}

// ---------------- host ----------------
static void launch_gemm(const float* A, const float* B, float* C, __half* Ch, int M, int K,
                        int N, int transB) {
    if (M < 2048) {
        dim3 gg((N + 63) / 64, (M + 31) / 32);
        gemm32_kernel<<<gg, 256>>>(A, B, C, Ch, M, K, N, transB);
    } else {
        dim3 gg((N + 63) / 64, (M + 63) / 64);
        gemm_kernel<<<gg, 256>>>(A, nullptr, K, B, C, Ch, M, K, N, transB);
    }
}

static void run_attn(int n, int n16, int pad64, __half* P, int LDP, const float* avec,
                     const int* rp, const int* ci, float* outp, int mode, const float* add,
                     float* Wh, __half* WhH, float* f1, float* f2, float* Zb) {
    whpad_kernel<<<1, 256>>>(WhH, n, n16);
    attn_coef_kernel<<<(n * 32 + 255) / 256, 256>>>(Wh, avec, f1, f2, n);
    pbuild_kernel<<<n, 256>>>(rp, ci, f1, f2, P, LDP, Zb);
    zfix_kernel<<<n, 256>>>(P, LDP, Zb, n);
    dim3 gg(5, pad64 / 64);
    wmma_spmm_kernel<<<gg, 256>>>(P, LDP, WhH, Zb, outp, add, n, n16, mode);
}

extern "C" void kernel_launch(void* const* d_in, const int* in_sizes, int n_in,
                              void* d_out, int out_size) {
    const float* A = (const float*)d_in[0];
    const float* X = (const float*)d_in[1];
    const float* start_W = (const float*)d_in[2];
    const float* start_a = (const float*)d_in[3];
    const float* bottom_W = (const float*)d_in[4];
    const float* bottom_a = (const float*)d_in[5];
    const float* end_W = (const float*)d_in[6];
    const float* end_a = (const float*)d_in[7];
    const float* down_W = (const float*)d_in[8];
    const float* down_a = (const float*)d_in[9];
    const float* up_W = (const float*)d_in[10];
    const float* up_a = (const float*)d_in[11];
    const float* pool_w = (const float*)d_in[12];
    const float* pool_b = (const float*)d_in[13];
    const float* unpool_w = (const float*)d_in[14];
    const float* unpool_b = (const float*)d_in[15];
    float* outp = (float*)d_out;

    static const int ns[5] = {4096, 3686, 2580, 1548, 774};
    static const int n16s[5] = {4096, 3696, 2592, 1552, 784};
    static const int pad64s[5] = {4096, 3712, 2624, 1600, 832};
    static const size_t poffs[5] = {0ULL, 16777216ULL, 30556160ULL, 37441536ULL, 40001536ULL};
    static const int sortP[4] = {4096, 4096, 4096, 2048};

    int* rp_base;
    int* ci_base;
    int* idx_base;
    int* rank_base;
    float *v, *XC, *Wh, *f1, *f2, *Zb, *orgX, *downb, *Hbuf, *Ubuf, *scores, *vals;
    __half* WhH;
    __half* Pbase;
    cudaGetSymbolAddress((void**)&rp_base, g_rp);
    cudaGetSymbolAddress((void**)&ci_base, g_ci);
    cudaGetSymbolAddress((void**)&idx_base, g_idx);
    cudaGetSymbolAddress((void**)&rank_base, g_rankL);
    cudaGetSymbolAddress((void**)&v, g_v);
    cudaGetSymbolAddress((void**)&XC, g_XC);
    cudaGetSymbolAddress((void**)&Wh, g_Wh);
    cudaGetSymbolAddress((void**)&WhH, g_WhH);
    cudaGetSymbolAddress((void**)&f1, g_f1);
    cudaGetSymbolAddress((void**)&f2, g_f2);
    cudaGetSymbolAddress((void**)&Zb, g_Z);
    cudaGetSymbolAddress((void**)&Pbase, g_P);
    cudaGetSymbolAddress((void**)&orgX, g_orgX);
    cudaGetSymbolAddress((void**)&downb, g_down);
    cudaGetSymbolAddress((void**)&Hbuf, g_Hbuf);
    cudaGetSymbolAddress((void**)&Ubuf, g_Ubuf);
    cudaGetSymbolAddress((void**)&scores, g_scores);
    cudaGetSymbolAddress((void**)&vals, g_vals);

    int* rp0 = rp_base;
    int* ci0 = ci_base;

    // build level-0 CSR
    csr0_count<<<N0, 256>>>(A);
    scan_kernel<<<1, 1024>>>(rp0, N0);
    csr0_fill<<<N0, 256>>>(A, rp0, ci0);

    // eigenvector centrality: 30 power iterations, one persistent kernel
    centrality_fused<<<CBLOCKS, 1024>>>(rp0, ci0);

    // Xc = [X | centrality]
    concat_xc_kernel<<<(N0 * D + 255) / 256, 256>>>(X, v, XC);

    // start GAT -> orgX   (level 0)
    launch_gemm(XC, start_W, Wh, WhH, N0, D, 320, 0);
    run_attn(ns[0], n16s[0], pad64s[0], Pbase + poffs[0], pad64s[0], start_a, rp0, ci0,
             orgX, 1, nullptr, Wh, WhH, f1, f2, Zb);

    // down path
    for (int i = 0; i < 4; i++) {
        int* rpi = rp_base + i * (N0 + 1);
        int* cii = ci_base + (size_t)i * NNZMAX;
        int* rpn = rp_base + (i + 1) * (N0 + 1);
        int* cin = ci_base + (size_t)(i + 1) * NNZMAX;
        int* idxi = idx_base + (size_t)i * N0;
        int* ranki = rank_base + (size_t)i * N0;
        float* dout = downb + (size_t)i * N0 * D;
        const float* Hin = (i == 0) ? orgX : Hbuf;
        launch_gemm(Hin, down_W + (size_t)i * D * D, Wh, WhH, ns[i], D, 320, 0);
        run_attn(ns[i], n16s[i], pad64s[i], Pbase + poffs[i], pad64s[i],
                 down_a + (size_t)i * 2 * D, rpi, cii, dout, 1, nullptr, Wh, WhH, f1, f2, Zb);
        // pool
        pool_score_kernel<<<(ns[i] * 32 + 255) / 256, 256>>>(dout, pool_w + (size_t)i * D,
                                                             pool_b + i, scores, ns[i]);
        sort_kernel<<<1, 1024>>>(scores, vals, idxi, ns[i], sortP[i]);
        poolx_kernel<<<(ns[i + 1] * D + 255) / 256, 256>>>(dout, idxi, vals, Hbuf, ns[i + 1]);
        rank_init_kernel<<<(ns[i] + 255) / 256, 256>>>(ranki, ns[i]);
        rank_set_kernel<<<(ns[i + 1] + 255) / 256, 256>>>(idxi, ranki, ns[i + 1]);
        pool_deg_kernel<<<(ns[i + 1] * 32 + 255) / 256, 256>>>(rpi, cii, idxi, ranki, ns[i + 1]);
        scan_kernel<<<1, 1024>>>(rpn, ns[i + 1]);
        pool_fill_kernel<<<(ns[i + 1] * 32 + 255) / 256, 256>>>(rpi, cii, rpn, cin, idxi,
                                                                ranki, ns[i + 1]);
    }

    // bottom GAT (level 4)
    launch_gemm(Hbuf, bottom_W, Wh, WhH, ns[4], D, 320, 0);
    run_attn(ns[4], n16s[4], pad64s[4], Pbase + poffs[4], pad64s[4], bottom_a,
             rp_base + 4 * (N0 + 1), ci_base + (size_t)4 * NNZMAX, Hbuf, 1, nullptr,
             Wh, WhH, f1, f2, Zb);

    // up path
    for (int i = 0; i < 4; i++) {
        int lu = 3 - i;
        int nl = ns[lu], nc = ns[lu + 1];
        int* rpl = rp_base + lu * (N0 + 1);
        int* cil = ci_base + (size_t)lu * NNZMAX;
        int* rankl = rank_base + (size_t)lu * N0;
        launch_gemm(Hbuf, unpool_w + (size_t)i * D * D, Wh, nullptr, nc, D, D, 1);
        unpool_fused_kernel<<<(nl * D + 255) / 256, 256>>>(Hbuf, Wh,
                                                           unpool_b + (size_t)i * D, rankl,
                                                           Ubuf, nl);
        launch_gemm(Ubuf, up_W + (size_t)i * D * D, Wh, WhH, nl, D, 320, 0);
        run_attn(nl, n16s[lu], pad64s[lu], Pbase + poffs[lu], pad64s[lu],
                 up_a + (size_t)i * 2 * D, rpl, cil, Hbuf, 2, downb + (size_t)lu * N0 * D,
                 Wh, WhH, f1, f2, Zb);
    }

    // end GAT on [H | orgX] with level-0 adjacency, no elu; concat fused into GEMM
    {
        dim3 gg((320 + 63) / 64, (N0 + 63) / 64);
        gemm_kernel<<<gg, 256>>>(Hbuf, orgX, 320, end_W, Wh, WhH, N0, 2 * D, 320, 0);
        run_attn(ns[0], n16s[0], pad64s[0], Pbase + poffs[0], pad64s[0], end_a, rp0, ci0,
                 outp, 0, nullptr, Wh, WhH, f1, f2, Zb);
    }

    // second output: start_gat_outs
    cudaMemcpyAsync(outp + (size_t)N0 * D, orgX, (size_t)N0 * D * sizeof(float),
                    cudaMemcpyDeviceToDevice);
}